// round 1
// baseline (speedup 1.0000x reference)
#include <cuda_runtime.h>
#include <math.h>

// ---------------- problem constants ----------------
#define BB    8
#define SS    2048
#define DD    512
#define MM    (BB*SS)          // 16384 rows
#define DM    (DD*4)           // 2048
#define KCONV 9
#define SPAD  (SS+8)           // 2056 padded rows per batch
#define NC    32               // scan chunks
#define LCH   (SS/NC)          // 64 steps per chunk

// ---------------- scratch (device globals; no allocs allowed) ----------------
__device__ float g_xn  [MM*DD];
__device__ float g_l1  [MM*DD];
__device__ float g_l2  [MM*DD];
__device__ float g_pad [BB*SPAD*DD];
__device__ float g_conv[MM*DD];
__device__ float g_xL  [MM*DD];
__device__ float g_R   [MM*DD];   // becomes a
__device__ float g_I   [MM*DD];   // becomes b
__device__ float g_H   [MM*DD];
__device__ float g_x1  [MM*DD];
__device__ float g_xn2 [MM*DD];
__device__ float g_act [MM*DM];
__device__ float g_Wc  [KCONV*DD*DD];
__device__ float g_pwT [DD*DD];
__device__ float g_cA  [BB*NC*DD];
__device__ float g_cB  [BB*NC*DD];
__device__ float g_pref[BB*NC*DD];

// ---------------- helpers ----------------
__device__ __forceinline__ float gelu_exact(float v) {
    return 0.5f * v * (1.0f + erff(v * 0.70710678118654752f));
}

// ---------------- RMS norm: x/(||x||+eps)*sqrt(D)*g ----------------
__global__ void rms_k(const float* __restrict__ x, const float* __restrict__ g,
                      float* __restrict__ o) {
    int row = blockIdx.x;
    int t = threadIdx.x;                       // 128 threads, 4 floats each
    const float4* xr = (const float4*)(x + (size_t)row * DD);
    float4 v = xr[t];
    float s = v.x*v.x + v.y*v.y + v.z*v.z + v.w*v.w;
    #pragma unroll
    for (int off = 16; off; off >>= 1) s += __shfl_xor_sync(0xffffffffu, s, off);
    __shared__ float ws[4];
    if ((t & 31) == 0) ws[t >> 5] = s;
    __syncthreads();
    float tot = ws[0] + ws[1] + ws[2] + ws[3];
    float sc = 22.627416997969522f / (sqrtf(tot) + 1e-6f);  // sqrt(512)/(norm+eps)
    float4 gv = ((const float4*)g)[t];
    float4 r;
    r.x = v.x * sc * gv.x; r.y = v.y * sc * gv.y;
    r.z = v.z * sc * gv.z; r.w = v.w * sc * gv.w;
    ((float4*)(o + (size_t)row * DD))[t] = r;
}

// ---------------- tiled SGEMM, C[M,N] = A[M,K]@B[K,N] + bias, epilogues ----------------
// EPI: 0 = bias only, 1 = sigmoid, 2 = gelu(v)*v (geglu-self), 3 = +res
#define BM 128
#define BN 128
#define BKK 8
#define TM 8
#define TN 8

template <int EPI>
__global__ void __launch_bounds__(256)
sgemm_k(const float* __restrict__ A, const float* __restrict__ Bw,
        const float* __restrict__ bias, const float* __restrict__ res,
        float* __restrict__ C, int M_, int N_, int K_) {
    __shared__ float As[BKK][BM];
    __shared__ float Bs[BKK][BN];
    int tid = threadIdx.x;
    int m0 = blockIdx.y * BM;
    int n0 = blockIdx.x * BN;
    int arow = tid >> 1;
    int acol = (tid & 1) * 4;
    int brow = tid >> 5;
    int bcol = (tid & 31) * 4;
    const float* Aptr = A + (size_t)(m0 + arow) * K_ + acol;
    const float* Bptr = Bw + (size_t)brow * N_ + n0 + bcol;
    int tx = tid & 15, ty = tid >> 4;
    float acc[TM][TN] = {};
    for (int k0 = 0; k0 < K_; k0 += BKK) {
        float4 av = *(const float4*)Aptr;
        As[acol + 0][arow] = av.x; As[acol + 1][arow] = av.y;
        As[acol + 2][arow] = av.z; As[acol + 3][arow] = av.w;
        *(float4*)(&Bs[brow][bcol]) = *(const float4*)Bptr;
        __syncthreads();
        #pragma unroll
        for (int kk = 0; kk < BKK; kk++) {
            float af[TM], bf[TN];
            *(float4*)(af)     = *(const float4*)(&As[kk][ty * TM]);
            *(float4*)(af + 4) = *(const float4*)(&As[kk][ty * TM + 4]);
            *(float4*)(bf)     = *(const float4*)(&Bs[kk][tx * TN]);
            *(float4*)(bf + 4) = *(const float4*)(&Bs[kk][tx * TN + 4]);
            #pragma unroll
            for (int i = 0; i < TM; i++)
                #pragma unroll
                for (int j = 0; j < TN; j++)
                    acc[i][j] += af[i] * bf[j];
        }
        __syncthreads();
        Aptr += BKK;
        Bptr += (size_t)BKK * N_;
    }
    #pragma unroll
    for (int i = 0; i < TM; i++) {
        int m = m0 + ty * TM + i;
        #pragma unroll
        for (int j = 0; j < TN; j++) {
            int n = n0 + tx * TN + j;
            float v = acc[i][j] + bias[n];
            if (EPI == 1) v = 1.0f / (1.0f + expf(-v));
            else if (EPI == 2) { float gg = gelu_exact(v); v = gg * v; }
            else if (EPI == 3) v += res[(size_t)m * N_ + n];
            C[(size_t)m * N_ + n] = v;
        }
    }
}

// ---------------- conv-as-GEMM: K' = 9*512 over padded activations ----------------
__global__ void __launch_bounds__(256)
sgemm_conv_k(const float* __restrict__ Apad, const float* __restrict__ Wc,
             const float* __restrict__ bias, float* __restrict__ C) {
    __shared__ float As[BKK][BM];
    __shared__ float Bs[BKK][BN];
    const int N_ = DD, K_ = KCONV * DD;
    int tid = threadIdx.x;
    int m0 = blockIdx.y * BM;
    int n0 = blockIdx.x * BN;
    int padbase = m0 + 8 * (m0 / SS);   // batch-adjusted padded row base
    int arow = tid >> 1;
    int acol = (tid & 1) * 4;
    int brow = tid >> 5;
    int bcol = (tid & 31) * 4;
    const float* Bptr = Wc + (size_t)brow * N_ + n0 + bcol;
    int tx = tid & 15, ty = tid >> 4;
    float acc[TM][TN] = {};
    for (int k0 = 0; k0 < K_; k0 += BKK) {
        int tap = k0 >> 9;
        int kin = k0 & 511;
        float4 av = *(const float4*)(Apad + (size_t)(padbase + arow + tap) * DD + kin + acol);
        As[acol + 0][arow] = av.x; As[acol + 1][arow] = av.y;
        As[acol + 2][arow] = av.z; As[acol + 3][arow] = av.w;
        *(float4*)(&Bs[brow][bcol]) = *(const float4*)Bptr;
        __syncthreads();
        #pragma unroll
        for (int kk = 0; kk < BKK; kk++) {
            float af[TM], bf[TN];
            *(float4*)(af)     = *(const float4*)(&As[kk][ty * TM]);
            *(float4*)(af + 4) = *(const float4*)(&As[kk][ty * TM + 4]);
            *(float4*)(bf)     = *(const float4*)(&Bs[kk][tx * TN]);
            *(float4*)(bf + 4) = *(const float4*)(&Bs[kk][tx * TN + 4]);
            #pragma unroll
            for (int i = 0; i < TM; i++)
                #pragma unroll
                for (int j = 0; j < TN; j++)
                    acc[i][j] += af[i] * bf[j];
        }
        __syncthreads();
        Bptr += (size_t)BKK * N_;
    }
    #pragma unroll
    for (int i = 0; i < TM; i++) {
        int m = m0 + ty * TM + i;
        #pragma unroll
        for (int j = 0; j < TN; j++) {
            int n = n0 + tx * TN + j;
            C[(size_t)m * N_ + n] = acc[i][j] + bias[n];
        }
    }
}

// ---------------- weight prep ----------------
__global__ void prep_wc_k(const float* __restrict__ dw_w, float* __restrict__ Wc) {
    int idx = blockIdx.x * blockDim.x + threadIdx.x;   // over 9*512*512
    if (idx >= KCONV * DD * DD) return;
    int o = idx % DD;
    int i = (idx / DD) % DD;
    int k = idx / (DD * DD);
    Wc[idx] = dw_w[((size_t)o * DD + i) * KCONV + k];
}

__global__ void prep_pwt_k(const float* __restrict__ pw_w, float* __restrict__ pwT) {
    int idx = blockIdx.x * blockDim.x + threadIdx.x;   // over 512*512
    if (idx >= DD * DD) return;
    int o = idx % DD;
    int i = idx / DD;
    pwT[idx] = pw_w[(size_t)o * DD + i];   // pwT[i][o] = pw_w[o][i][0]
}

// ---------------- zero-pad l1 per batch (4 left, 4 right) ----------------
__global__ void pad_k(const float* __restrict__ l1, float* __restrict__ pad) {
    size_t idx = (size_t)blockIdx.x * blockDim.x + threadIdx.x;   // over B*SPAD*DD/4 float4s
    size_t total = (size_t)BB * SPAD * DD / 4;
    if (idx >= total) return;
    size_t row = idx / (DD / 4);
    int c4 = (int)(idx % (DD / 4));
    int b = (int)(row / SPAD);
    int p = (int)(row % SPAD);
    float4 v = make_float4(0.f, 0.f, 0.f, 0.f);
    if (p >= 4 && p < SS + 4)
        v = ((const float4*)(l1 + ((size_t)b * SS + (p - 4)) * DD))[c4];
    ((float4*)(pad + row * DD))[c4] = v;
}

// ---------------- gate transform: R,I -> a,b ----------------
__global__ void gates_k(float* __restrict__ R, float* __restrict__ I,
                        const float* __restrict__ xL, const float* __restrict__ lam) {
    size_t i = (size_t)blockIdx.x * blockDim.x + threadIdx.x;
    if (i >= (size_t)MM * DD) return;
    int d = (int)(i & (DD - 1));
    float l = lam[d];
    float sp = (l > 15.f) ? l : log1pf(expf(l));
    float a = expf(-8.0f * sp * R[i]);
    float b = sqrtf(fmaxf(0.f, 1.0f - a * a)) * (I[i] * xL[i]);
    R[i] = a;
    I[i] = b;
}

// ---------------- chunked linear scan: h_t = a_t h_{t-1} + b_t ----------------
__global__ void scanA_k(const float* __restrict__ a, const float* __restrict__ b,
                        float* __restrict__ cA, float* __restrict__ cB) {
    int t = blockIdx.x * blockDim.x + threadIdx.x;     // B*NC*DD items
    if (t >= BB * NC * DD) return;
    int d = t & (DD - 1);
    int chunk = (t >> 9) & (NC - 1);
    int batch = t >> 14;
    size_t base = ((size_t)batch * SS + (size_t)chunk * LCH) * DD + d;
    float A = 1.f, Bv = 0.f;
    for (int s = 0; s < LCH; s++) {
        float av = a[base + (size_t)s * DD];
        float bv = b[base + (size_t)s * DD];
        Bv = av * Bv + bv;
        A *= av;
    }
    cA[t] = A; cB[t] = Bv;
}

__global__ void scanB_k(const float* __restrict__ cA, const float* __restrict__ cB,
                        float* __restrict__ pref) {
    int t = blockIdx.x * blockDim.x + threadIdx.x;     // B*DD items
    if (t >= BB * DD) return;
    int d = t & (DD - 1);
    int batch = t >> 9;
    float h = 0.f;
    for (int c = 0; c < NC; c++) {
        size_t idx = ((size_t)batch * NC + c) * DD + d;
        pref[idx] = h;
        h = cA[idx] * h + cB[idx];
    }
}

__global__ void scanC_k(const float* __restrict__ a, const float* __restrict__ b,
                        const float* __restrict__ pref, float* __restrict__ H) {
    int t = blockIdx.x * blockDim.x + threadIdx.x;
    if (t >= BB * NC * DD) return;
    int d = t & (DD - 1);
    int chunk = (t >> 9) & (NC - 1);
    int batch = t >> 14;
    size_t base = ((size_t)batch * SS + (size_t)chunk * LCH) * DD + d;
    float h = pref[t];
    for (int s = 0; s < LCH; s++) {
        size_t idx = base + (size_t)s * DD;
        h = a[idx] * h + b[idx];
        H[idx] = h;
    }
}

// ---------------- x1 = H * gelu(l2) + skip ----------------
__global__ void mix_k(const float* __restrict__ H, const float* __restrict__ l2,
                      const float* __restrict__ skip, float* __restrict__ x1) {
    size_t i = (size_t)blockIdx.x * blockDim.x + threadIdx.x;
    if (i >= (size_t)MM * DD) return;
    x1[i] = H[i] * gelu_exact(l2[i]) + skip[i];
}

// ---------------- launch ----------------
extern "C" void kernel_launch(void* const* d_in, const int* in_sizes, int n_in,
                              void* d_out, int out_size) {
    const float* x    = (const float*)d_in[0];
    const float* g    = (const float*)d_in[1];
    const float* W1   = (const float*)d_in[2];
    const float* b1   = (const float*)d_in[3];
    const float* W2   = (const float*)d_in[4];
    const float* b2   = (const float*)d_in[5];
    const float* dw_w = (const float*)d_in[6];
    const float* dw_b = (const float*)d_in[7];
    const float* pw_w = (const float*)d_in[8];
    const float* pw_b = (const float*)d_in[9];
    const float* Wi   = (const float*)d_in[10];
    const float* bi   = (const float*)d_in[11];
    const float* Wr   = (const float*)d_in[12];
    const float* br   = (const float*)d_in[13];
    const float* lam  = (const float*)d_in[14];
    const float* Wm1  = (const float*)d_in[15];
    const float* bm1  = (const float*)d_in[16];
    const float* Wm2  = (const float*)d_in[17];
    const float* bm2  = (const float*)d_in[18];
    float* out = (float*)d_out;

    float *xn, *l1, *l2, *pad, *conv, *xL, *R, *I, *H, *x1, *xn2, *act;
    float *Wc, *pwT, *cA, *cB, *pref;
    cudaGetSymbolAddress((void**)&xn,  g_xn);
    cudaGetSymbolAddress((void**)&l1,  g_l1);
    cudaGetSymbolAddress((void**)&l2,  g_l2);
    cudaGetSymbolAddress((void**)&pad, g_pad);
    cudaGetSymbolAddress((void**)&conv,g_conv);
    cudaGetSymbolAddress((void**)&xL,  g_xL);
    cudaGetSymbolAddress((void**)&R,   g_R);
    cudaGetSymbolAddress((void**)&I,   g_I);
    cudaGetSymbolAddress((void**)&H,   g_H);
    cudaGetSymbolAddress((void**)&x1,  g_x1);
    cudaGetSymbolAddress((void**)&xn2, g_xn2);
    cudaGetSymbolAddress((void**)&act, g_act);
    cudaGetSymbolAddress((void**)&Wc,  g_Wc);
    cudaGetSymbolAddress((void**)&pwT, g_pwT);
    cudaGetSymbolAddress((void**)&cA,  g_cA);
    cudaGetSymbolAddress((void**)&cB,  g_cB);
    cudaGetSymbolAddress((void**)&pref,g_pref);

    dim3 g512(DD / BN, MM / BM);          // (4, 128)
    dim3 g2048(DM / BN, MM / BM);         // (16, 128)

    // weight prep
    prep_wc_k<<<(KCONV * DD * DD + 255) / 256, 256>>>(dw_w, Wc);
    prep_pwt_k<<<(DD * DD + 255) / 256, 256>>>(pw_w, pwT);

    // block 1
    rms_k<<<MM, 128>>>(x, g, xn);
    sgemm_k<0><<<g512, 256>>>(xn, W1, b1, nullptr, l1, MM, DD, DD);
    sgemm_k<0><<<g512, 256>>>(xn, W2, b2, nullptr, l2, MM, DD, DD);
    pad_k<<<(BB * SPAD * DD / 4 + 255) / 256, 256>>>(l1, pad);
    sgemm_conv_k<<<g512, 256>>>(pad, Wc, dw_b, conv);
    sgemm_k<0><<<g512, 256>>>(conv, pwT, pw_b, nullptr, xL, MM, DD, DD);
    sgemm_k<1><<<g512, 256>>>(xL, Wr, br, nullptr, R, MM, DD, DD);
    sgemm_k<1><<<g512, 256>>>(xL, Wi, bi, nullptr, I, MM, DD, DD);
    gates_k<<<((size_t)MM * DD + 255) / 256, 256>>>(R, I, xL, lam);
    scanA_k<<<(BB * NC * DD + 255) / 256, 256>>>(R, I, cA, cB);
    scanB_k<<<(BB * DD + 255) / 256, 256>>>(cA, cB, pref);
    scanC_k<<<(BB * NC * DD + 255) / 256, 256>>>(R, I, pref, H);
    mix_k<<<((size_t)MM * DD + 255) / 256, 256>>>(H, l2, x, x1);

    // block 2 (MLP)
    rms_k<<<MM, 128>>>(x1, g, xn2);
    sgemm_k<2><<<g2048, 256>>>(xn2, Wm1, bm1, nullptr, act, MM, DM, DD);
    sgemm_k<3><<<g512, 256>>>(act, Wm2, bm2, x1, out, MM, DD, DM);
}

// round 2
// speedup vs baseline: 2.8163x; 2.8163x over previous
#include <cuda_runtime.h>
#include <math.h>

// ---------------- problem constants ----------------
#define BB    8
#define SS    2048
#define DD    512
#define MM    (BB*SS)          // 16384 rows
#define DM    (DD*4)           // 2048
#define KCONV 9
#define SPAD  (SS+8)           // 2056 padded rows per batch
#define NC    32               // scan chunks
#define LCH   (SS/NC)          // 64 steps per chunk

// ---------------- scratch (device globals; no allocs allowed) ----------------
__device__ float g_xn  [MM*DD];
__device__ float g_l1  [MM*DD];
__device__ float g_l2  [MM*DD];
__device__ float g_pad [BB*SPAD*DD];
__device__ float g_conv[MM*DD];
__device__ float g_xL  [MM*DD];
__device__ float g_R   [MM*DD];   // becomes a
__device__ float g_I   [MM*DD];   // becomes b
__device__ float g_x1  [MM*DD];
__device__ float g_xn2 [MM*DD];
__device__ float g_act [MM*DM];
__device__ float g_Wc  [KCONV*DD*DD];
__device__ float g_pwT [DD*DD];
__device__ float g_cA  [BB*NC*DD];
__device__ float g_cB  [BB*NC*DD];
__device__ float g_pref[BB*NC*DD];

// ---------------- helpers ----------------
__device__ __forceinline__ float gelu_exact(float v) {
    return 0.5f * v * (1.0f + erff(v * 0.70710678118654752f));
}

__device__ __forceinline__ unsigned f2t(float f) {
    unsigned u;
    asm("cvt.rna.tf32.f32 %0, %1;" : "=r"(u) : "f"(f));
    return u;
}

__device__ __forceinline__ void mma8(float* c, const unsigned* a, const unsigned* b) {
    asm volatile(
        "mma.sync.aligned.m16n8k8.row.col.f32.tf32.tf32.f32 "
        "{%0,%1,%2,%3}, {%4,%5,%6,%7}, {%8,%9}, {%0,%1,%2,%3};"
        : "+f"(c[0]), "+f"(c[1]), "+f"(c[2]), "+f"(c[3])
        : "r"(a[0]), "r"(a[1]), "r"(a[2]), "r"(a[3]), "r"(b[0]), "r"(b[1]));
}

__device__ __forceinline__ void cpa16(unsigned s, const float* g) {
    asm volatile("cp.async.ca.shared.global [%0], [%1], 16;" :: "r"(s), "l"(g));
}
__device__ __forceinline__ void cpa_commit() {
    asm volatile("cp.async.commit_group;");
}

// ---------------- RMS norm ----------------
__global__ void rms_k(const float* __restrict__ x, const float* __restrict__ g,
                      float* __restrict__ o) {
    int row = blockIdx.x;
    int t = threadIdx.x;
    const float4* xr = (const float4*)(x + (size_t)row * DD);
    float4 v = xr[t];
    float s = v.x*v.x + v.y*v.y + v.z*v.z + v.w*v.w;
    #pragma unroll
    for (int off = 16; off; off >>= 1) s += __shfl_xor_sync(0xffffffffu, s, off);
    __shared__ float ws[4];
    if ((t & 31) == 0) ws[t >> 5] = s;
    __syncthreads();
    float tot = ws[0] + ws[1] + ws[2] + ws[3];
    float sc = 22.627416997969522f / (sqrtf(tot) + 1e-6f);
    float4 gv = ((const float4*)g)[t];
    float4 r;
    r.x = v.x * sc * gv.x; r.y = v.y * sc * gv.y;
    r.z = v.z * sc * gv.z; r.w = v.w * sc * gv.w;
    ((float4*)(o + (size_t)row * DD))[t] = r;
}

// ---------------- tensor-core tf32 GEMM ----------------
// C[M,N] = A[M,K] @ B[K,N] + bias, epilogues:
// EPI: 0 = bias only, 1 = sigmoid, 2 = gelu(v)*v, 3 = +res
// CONV: A is read from the padded activation buffer with tap offsets (K'=9*512)
#define BM 128
#define BN 128
#define BK 16
#define APITCH (BK + 4)    // 20 -> conflict-free A frag LDS
#define BPITCH (BN + 8)    // 136 -> conflict-free B frag LDS

template <int EPI, bool CONV>
__global__ void __launch_bounds__(256)
tgemm(const float* __restrict__ A, const float* __restrict__ Bw,
      const float* __restrict__ bias, const float* __restrict__ res,
      float* __restrict__ C, int M_, int N_, int K_) {
    __shared__ float As[2][BM][APITCH];
    __shared__ float Bs[2][BK][BPITCH];

    const int tid = threadIdx.x;
    const int m0 = blockIdx.y * BM;
    const int n0 = blockIdx.x * BN;
    const int warp = tid >> 5, lane = tid & 31;
    const int r = lane >> 2, cg = lane & 3;
    const int wm = (warp >> 2) * 64;      // warp row base (2 warp-rows)
    const int wn = (warp & 3) * 32;       // warp col base (4 warp-cols)
    const int padbase = CONV ? (m0 + 8 * (m0 / SS)) : 0;

    // A staging: thread -> row ar, two float4s at float-col ac, ac+4
    const int ar = tid >> 1;
    const int ac = (tid & 1) * 8;
    // B staging: thread -> rows br, br+8, float4 col bc
    const int br = tid >> 5;
    const int bc = (tid & 31) * 4;

    const int nit = K_ / BK;

    auto prefetch = [&](int it, int buf) {
        int k0 = it * BK;
        const float* ga;
        if (CONV) {
            int tap = k0 >> 9;
            int kin = k0 & 511;
            ga = A + (size_t)(padbase + ar + tap) * DD + kin + ac;
        } else {
            ga = A + (size_t)(m0 + ar) * K_ + k0 + ac;
        }
        unsigned da = (unsigned)__cvta_generic_to_shared(&As[buf][ar][ac]);
        cpa16(da, ga);
        cpa16(da + 16, ga + 4);
        const float* gb = Bw + (size_t)(k0 + br) * N_ + n0 + bc;
        cpa16((unsigned)__cvta_generic_to_shared(&Bs[buf][br][bc]), gb);
        cpa16((unsigned)__cvta_generic_to_shared(&Bs[buf][br + 8][bc]), gb + (size_t)8 * N_);
    };

    float acc[4][4][4] = {};

    prefetch(0, 0);
    cpa_commit();

    for (int it = 0; it < nit; it++) {
        if (it + 1 < nit) {
            prefetch(it + 1, (it + 1) & 1);
            cpa_commit();
            asm volatile("cp.async.wait_group 1;");
        } else {
            cpa_commit();
            asm volatile("cp.async.wait_group 0;");
        }
        __syncthreads();
        const int buf = it & 1;
        #pragma unroll
        for (int t = 0; t < 2; t++) {
            unsigned af[4][4], bf[4][2];
            #pragma unroll
            for (int mi = 0; mi < 4; mi++) {
                int row = wm + mi * 16 + r;
                af[mi][0] = f2t(As[buf][row    ][8 * t + cg]);
                af[mi][1] = f2t(As[buf][row + 8][8 * t + cg]);
                af[mi][2] = f2t(As[buf][row    ][8 * t + cg + 4]);
                af[mi][3] = f2t(As[buf][row + 8][8 * t + cg + 4]);
            }
            #pragma unroll
            for (int ni = 0; ni < 4; ni++) {
                int col = wn + ni * 8 + r;
                bf[ni][0] = f2t(Bs[buf][8 * t + cg    ][col]);
                bf[ni][1] = f2t(Bs[buf][8 * t + cg + 4][col]);
            }
            #pragma unroll
            for (int mi = 0; mi < 4; mi++)
                #pragma unroll
                for (int ni = 0; ni < 4; ni++)
                    mma8(acc[mi][ni], af[mi], bf[ni]);
        }
        __syncthreads();
    }

    // epilogue
    #pragma unroll
    for (int mi = 0; mi < 4; mi++) {
        int mlo = m0 + wm + mi * 16 + r;
        int mhi = mlo + 8;
        #pragma unroll
        for (int ni = 0; ni < 4; ni++) {
            int n = n0 + wn + ni * 8 + 2 * cg;
            float b0 = bias[n], b1 = bias[n + 1];
            float v0 = acc[mi][ni][0] + b0;
            float v1 = acc[mi][ni][1] + b1;
            float v2 = acc[mi][ni][2] + b0;
            float v3 = acc[mi][ni][3] + b1;
            if (EPI == 1) {
                v0 = 1.0f / (1.0f + expf(-v0)); v1 = 1.0f / (1.0f + expf(-v1));
                v2 = 1.0f / (1.0f + expf(-v2)); v3 = 1.0f / (1.0f + expf(-v3));
            } else if (EPI == 2) {
                v0 *= gelu_exact(v0); v1 *= gelu_exact(v1);
                v2 *= gelu_exact(v2); v3 *= gelu_exact(v3);
            } else if (EPI == 3) {
                float2 r0 = *(const float2*)(res + (size_t)mlo * N_ + n);
                float2 r1 = *(const float2*)(res + (size_t)mhi * N_ + n);
                v0 += r0.x; v1 += r0.y; v2 += r1.x; v3 += r1.y;
            }
            *(float2*)(C + (size_t)mlo * N_ + n) = make_float2(v0, v1);
            *(float2*)(C + (size_t)mhi * N_ + n) = make_float2(v2, v3);
        }
    }
}

// ---------------- weight prep ----------------
__global__ void prep_wc_k(const float* __restrict__ dw_w, float* __restrict__ Wc) {
    int idx = blockIdx.x * blockDim.x + threadIdx.x;
    if (idx >= KCONV * DD * DD) return;
    int o = idx % DD;
    int i = (idx / DD) % DD;
    int k = idx / (DD * DD);
    Wc[idx] = dw_w[((size_t)o * DD + i) * KCONV + k];
}

__global__ void prep_pwt_k(const float* __restrict__ pw_w, float* __restrict__ pwT) {
    int idx = blockIdx.x * blockDim.x + threadIdx.x;
    if (idx >= DD * DD) return;
    int o = idx % DD;
    int i = idx / DD;
    pwT[idx] = pw_w[(size_t)o * DD + i];
}

// ---------------- zero-pad l1 per batch (4 left, 4 right) ----------------
__global__ void pad_k(const float* __restrict__ l1, float* __restrict__ pad) {
    size_t idx = (size_t)blockIdx.x * blockDim.x + threadIdx.x;
    size_t total = (size_t)BB * SPAD * DD / 4;
    if (idx >= total) return;
    size_t row = idx / (DD / 4);
    int c4 = (int)(idx % (DD / 4));
    int b = (int)(row / SPAD);
    int p = (int)(row % SPAD);
    float4 v = make_float4(0.f, 0.f, 0.f, 0.f);
    if (p >= 4 && p < SS + 4)
        v = ((const float4*)(l1 + ((size_t)b * SS + (p - 4)) * DD))[c4];
    ((float4*)(pad + row * DD))[c4] = v;
}

// ---------------- gate transform: R,I -> a,b ----------------
__global__ void gates_k(float* __restrict__ R, float* __restrict__ I,
                        const float* __restrict__ xL, const float* __restrict__ lam) {
    size_t i = (size_t)blockIdx.x * blockDim.x + threadIdx.x;
    if (i >= (size_t)MM * DD) return;
    int d = (int)(i & (DD - 1));
    float l = lam[d];
    float sp = (l > 15.f) ? l : log1pf(expf(l));
    float a = expf(-8.0f * sp * R[i]);
    float b = sqrtf(fmaxf(0.f, 1.0f - a * a)) * (I[i] * xL[i]);
    R[i] = a;
    I[i] = b;
}

// ---------------- chunked linear scan ----------------
__global__ void scanA_k(const float* __restrict__ a, const float* __restrict__ b,
                        float* __restrict__ cA, float* __restrict__ cB) {
    int t = blockIdx.x * blockDim.x + threadIdx.x;
    if (t >= BB * NC * DD) return;
    int d = t & (DD - 1);
    int chunk = (t >> 9) & (NC - 1);
    int batch = t >> 14;
    size_t base = ((size_t)batch * SS + (size_t)chunk * LCH) * DD + d;
    float A = 1.f, Bv = 0.f;
    for (int s = 0; s < LCH; s++) {
        float av = a[base + (size_t)s * DD];
        float bv = b[base + (size_t)s * DD];
        Bv = av * Bv + bv;
        A *= av;
    }
    cA[t] = A; cB[t] = Bv;
}

__global__ void scanB_k(const float* __restrict__ cA, const float* __restrict__ cB,
                        float* __restrict__ pref) {
    int t = blockIdx.x * blockDim.x + threadIdx.x;
    if (t >= BB * DD) return;
    int d = t & (DD - 1);
    int batch = t >> 9;
    float h = 0.f;
    for (int c = 0; c < NC; c++) {
        size_t idx = ((size_t)batch * NC + c) * DD + d;
        pref[idx] = h;
        h = cA[idx] * h + cB[idx];
    }
}

// scanC fused with mix: x1 = h * gelu(l2) + skip
__global__ void scanC_k(const float* __restrict__ a, const float* __restrict__ b,
                        const float* __restrict__ pref, const float* __restrict__ l2,
                        const float* __restrict__ skip, float* __restrict__ x1) {
    int t = blockIdx.x * blockDim.x + threadIdx.x;
    if (t >= BB * NC * DD) return;
    int d = t & (DD - 1);
    int chunk = (t >> 9) & (NC - 1);
    int batch = t >> 14;
    size_t base = ((size_t)batch * SS + (size_t)chunk * LCH) * DD + d;
    float h = pref[t];
    for (int s = 0; s < LCH; s++) {
        size_t idx = base + (size_t)s * DD;
        h = a[idx] * h + b[idx];
        x1[idx] = h * gelu_exact(l2[idx]) + skip[idx];
    }
}

// ---------------- launch ----------------
extern "C" void kernel_launch(void* const* d_in, const int* in_sizes, int n_in,
                              void* d_out, int out_size) {
    const float* x    = (const float*)d_in[0];
    const float* g    = (const float*)d_in[1];
    const float* W1   = (const float*)d_in[2];
    const float* b1   = (const float*)d_in[3];
    const float* W2   = (const float*)d_in[4];
    const float* b2   = (const float*)d_in[5];
    const float* dw_w = (const float*)d_in[6];
    const float* dw_b = (const float*)d_in[7];
    const float* pw_w = (const float*)d_in[8];
    const float* pw_b = (const float*)d_in[9];
    const float* Wi   = (const float*)d_in[10];
    const float* bi   = (const float*)d_in[11];
    const float* Wr   = (const float*)d_in[12];
    const float* br   = (const float*)d_in[13];
    const float* lam  = (const float*)d_in[14];
    const float* Wm1  = (const float*)d_in[15];
    const float* bm1  = (const float*)d_in[16];
    const float* Wm2  = (const float*)d_in[17];
    const float* bm2  = (const float*)d_in[18];
    float* out = (float*)d_out;

    float *xn, *l1, *l2, *pad, *conv, *xL, *R, *I, *x1, *xn2, *act;
    float *Wc, *pwT, *cA, *cB, *pref;
    cudaGetSymbolAddress((void**)&xn,  g_xn);
    cudaGetSymbolAddress((void**)&l1,  g_l1);
    cudaGetSymbolAddress((void**)&l2,  g_l2);
    cudaGetSymbolAddress((void**)&pad, g_pad);
    cudaGetSymbolAddress((void**)&conv,g_conv);
    cudaGetSymbolAddress((void**)&xL,  g_xL);
    cudaGetSymbolAddress((void**)&R,   g_R);
    cudaGetSymbolAddress((void**)&I,   g_I);
    cudaGetSymbolAddress((void**)&x1,  g_x1);
    cudaGetSymbolAddress((void**)&xn2, g_xn2);
    cudaGetSymbolAddress((void**)&act, g_act);
    cudaGetSymbolAddress((void**)&Wc,  g_Wc);
    cudaGetSymbolAddress((void**)&pwT, g_pwT);
    cudaGetSymbolAddress((void**)&cA,  g_cA);
    cudaGetSymbolAddress((void**)&cB,  g_cB);
    cudaGetSymbolAddress((void**)&pref,g_pref);

    dim3 g512(DD / BN, MM / BM);          // (4, 128)
    dim3 g2048(DM / BN, MM / BM);         // (16, 128)

    prep_wc_k<<<(KCONV * DD * DD + 255) / 256, 256>>>(dw_w, Wc);
    prep_pwt_k<<<(DD * DD + 255) / 256, 256>>>(pw_w, pwT);

    // block 1
    rms_k<<<MM, 128>>>(x, g, xn);
    tgemm<0, false><<<g512, 256>>>(xn, W1, b1, nullptr, l1, MM, DD, DD);
    tgemm<0, false><<<g512, 256>>>(xn, W2, b2, nullptr, l2, MM, DD, DD);
    pad_k<<<(BB * SPAD * DD / 4 + 255) / 256, 256>>>(l1, pad);
    tgemm<0, true ><<<g512, 256>>>(pad, Wc, dw_b, nullptr, conv, MM, DD, KCONV * DD);
    tgemm<0, false><<<g512, 256>>>(conv, pwT, pw_b, nullptr, xL, MM, DD, DD);
    tgemm<1, false><<<g512, 256>>>(xL, Wr, br, nullptr, R, MM, DD, DD);
    tgemm<1, false><<<g512, 256>>>(xL, Wi, bi, nullptr, I, MM, DD, DD);
    gates_k<<<((size_t)MM * DD + 255) / 256, 256>>>(R, I, xL, lam);
    scanA_k<<<(BB * NC * DD + 255) / 256, 256>>>(R, I, cA, cB);
    scanB_k<<<(BB * DD + 255) / 256, 256>>>(cA, cB, pref);
    scanC_k<<<(BB * NC * DD + 255) / 256, 256>>>(R, I, pref, l2, x, x1);

    // block 2 (MLP)
    rms_k<<<MM, 128>>>(x1, g, xn2);
    tgemm<2, false><<<g2048, 256>>>(xn2, Wm1, bm1, nullptr, act, MM, DM, DD);
    tgemm<3, false><<<g512, 256>>>(act, Wm2, bm2, x1, out, MM, DD, DM);
}

// round 3
// speedup vs baseline: 2.8858x; 1.0247x over previous
#include <cuda_runtime.h>
#include <math.h>

// ---------------- problem constants ----------------
#define BB    8
#define SS    2048
#define DD    512
#define MM    (BB*SS)          // 16384 rows
#define DM    (DD*4)           // 2048
#define KCONV 9
#define SPAD  (SS+8)           // 2056 padded rows per batch
#define NC    32               // scan chunks
#define LCH   (SS/NC)          // 64 steps per chunk

// ---------------- scratch (device globals; no allocs allowed) ----------------
__device__ float g_xn  [MM*DD];
__device__ float g_l2  [MM*DD];
__device__ float g_pad [BB*SPAD*DD];
__device__ float g_conv[MM*DD];
__device__ float g_xL  [MM*DD];
__device__ float g_R   [MM*DD];
__device__ float g_I   [MM*DD];
__device__ float g_x1  [MM*DD];
__device__ float g_xn2 [MM*DD];
__device__ float g_act [MM*DM];
__device__ float g_Wc  [KCONV*DD*DD];
__device__ float g_pwT [DD*DD];
__device__ float g_cA  [BB*NC*DD];
__device__ float g_cB  [BB*NC*DD];
__device__ float g_pref[BB*NC*DD];
__device__ float g_lamc[DD];
__device__ float g_W1t [DD*DD];
__device__ float g_W2t [DD*DD];
__device__ float g_Wrt [DD*DD];
__device__ float g_Wit [DD*DD];
__device__ float g_Wm1t[DD*DM];
__device__ float g_Wm2t[DD*DM];

// ---------------- helpers ----------------
__device__ __forceinline__ float gelu_exact(float v) {
    return 0.5f * v * (1.0f + erff(v * 0.70710678118654752f));
}

__device__ __forceinline__ float f2tf(float f) {
    unsigned u;
    asm("cvt.rna.tf32.f32 %0, %1;" : "=r"(u) : "f"(f));
    return __uint_as_float(u);
}

__device__ __forceinline__ void mma8(float* c, const unsigned* a, const unsigned* b) {
    asm volatile(
        "mma.sync.aligned.m16n8k8.row.col.f32.tf32.tf32.f32 "
        "{%0,%1,%2,%3}, {%4,%5,%6,%7}, {%8,%9}, {%0,%1,%2,%3};"
        : "+f"(c[0]), "+f"(c[1]), "+f"(c[2]), "+f"(c[3])
        : "r"(a[0]), "r"(a[1]), "r"(a[2]), "r"(a[3]), "r"(b[0]), "r"(b[1]));
}

__device__ __forceinline__ void cpa16(unsigned s, const float* g) {
    asm volatile("cp.async.ca.shared.global [%0], [%1], 16;" :: "r"(s), "l"(g));
}
__device__ __forceinline__ void cpa_commit() {
    asm volatile("cp.async.commit_group;");
}

// ---------------- RMS norm (output tf32-rounded: always feeds a GEMM) ----------------
__global__ void rms_k(const float* __restrict__ x, const float* __restrict__ g,
                      float* __restrict__ o) {
    int row = blockIdx.x;
    int t = threadIdx.x;
    const float4* xr = (const float4*)(x + (size_t)row * DD);
    float4 v = xr[t];
    float s = v.x*v.x + v.y*v.y + v.z*v.z + v.w*v.w;
    #pragma unroll
    for (int off = 16; off; off >>= 1) s += __shfl_xor_sync(0xffffffffu, s, off);
    __shared__ float ws[4];
    if ((t & 31) == 0) ws[t >> 5] = s;
    __syncthreads();
    float tot = ws[0] + ws[1] + ws[2] + ws[3];
    float sc = 22.627416997969522f / (sqrtf(tot) + 1e-6f);
    float4 gv = ((const float4*)g)[t];
    float4 r;
    r.x = f2tf(v.x * sc * gv.x); r.y = f2tf(v.y * sc * gv.y);
    r.z = f2tf(v.z * sc * gv.z); r.w = f2tf(v.w * sc * gv.w);
    ((float4*)(o + (size_t)row * DD))[t] = r;
}

// ---------------- tensor-core tf32 GEMM (pre-rounded operands) ----------------
#define BM 128
#define BN 128
#define BK 32
#define APITCH (BK + 4)    // 36
#define BPITCH (BN + 8)    // 136
#define ASZ (2*BM*APITCH)
#define SMEMSZ ((ASZ + 2*BK*BPITCH)*4)

template <int EPI, bool CONV, bool ROUND, bool PADOUT>
__global__ void __launch_bounds__(256, 2)
tgemm(const float* __restrict__ A, const float* __restrict__ Bw,
      const float* __restrict__ bias, const float* __restrict__ res,
      float* __restrict__ C, int M_, int N_, int K_) {
    extern __shared__ float sm[];
    float (*As)[BM][APITCH] = (float(*)[BM][APITCH])sm;
    float (*Bs)[BK][BPITCH] = (float(*)[BK][BPITCH])(sm + ASZ);

    const int tid = threadIdx.x;
    const int m0 = blockIdx.y * BM;
    const int n0 = blockIdx.x * BN;
    const int warp = tid >> 5, lane = tid & 31;
    const int r = lane >> 2, cg = lane & 3;
    const int wm = (warp >> 2) * 64;
    const int wn = (warp & 3) * 32;
    const int padbase = CONV ? (m0 + 8 * (m0 / SS)) : 0;

    const int ar = tid >> 1;
    const int ac = (tid & 1) * 16;
    const int br = tid >> 5;
    const int bc = (tid & 31) * 4;

    const int nit = K_ / BK;

    auto prefetch = [&](int it, int buf) {
        int k0 = it * BK;
        const float* ga;
        if (CONV) {
            int tap = k0 >> 9;
            int kin = k0 & 511;
            ga = A + (size_t)(padbase + ar + tap) * DD + kin + ac;
        } else {
            ga = A + (size_t)(m0 + ar) * K_ + k0 + ac;
        }
        unsigned da = (unsigned)__cvta_generic_to_shared(&As[buf][ar][ac]);
        cpa16(da,      ga);
        cpa16(da + 16, ga + 4);
        cpa16(da + 32, ga + 8);
        cpa16(da + 48, ga + 12);
        const float* gb = Bw + (size_t)(k0 + br) * N_ + n0 + bc;
        #pragma unroll
        for (int q = 0; q < 4; q++)
            cpa16((unsigned)__cvta_generic_to_shared(&Bs[buf][br + 8 * q][bc]),
                  gb + (size_t)(8 * q) * N_);
    };

    float acc[4][4][4] = {};

    prefetch(0, 0);
    cpa_commit();

    for (int it = 0; it < nit; it++) {
        if (it + 1 < nit) {
            prefetch(it + 1, (it + 1) & 1);
            cpa_commit();
            asm volatile("cp.async.wait_group 1;");
        } else {
            cpa_commit();
            asm volatile("cp.async.wait_group 0;");
        }
        __syncthreads();
        const int buf = it & 1;
        #pragma unroll
        for (int t = 0; t < 4; t++) {
            unsigned af[4][4], bf[4][2];
            const int k = 8 * t + cg;
            #pragma unroll
            for (int mi = 0; mi < 4; mi++) {
                int row = wm + mi * 16 + r;
                af[mi][0] = __float_as_uint(As[buf][row    ][k]);
                af[mi][1] = __float_as_uint(As[buf][row + 8][k]);
                af[mi][2] = __float_as_uint(As[buf][row    ][k + 4]);
                af[mi][3] = __float_as_uint(As[buf][row + 8][k + 4]);
            }
            #pragma unroll
            for (int ni = 0; ni < 4; ni++) {
                int col = wn + ni * 8 + r;
                bf[ni][0] = __float_as_uint(Bs[buf][k    ][col]);
                bf[ni][1] = __float_as_uint(Bs[buf][k + 4][col]);
            }
            #pragma unroll
            for (int mi = 0; mi < 4; mi++)
                #pragma unroll
                for (int ni = 0; ni < 4; ni++)
                    mma8(acc[mi][ni], af[mi], bf[ni]);
        }
        __syncthreads();
    }

    const int opitch = PADOUT ? DD : N_;
    #pragma unroll
    for (int mi = 0; mi < 4; mi++) {
        int mlo = m0 + wm + mi * 16 + r;
        int mhi = mlo + 8;
        int olo = PADOUT ? (mlo + 4 + 8 * (mlo >> 11)) : mlo;
        int ohi = PADOUT ? (mhi + 4 + 8 * (mhi >> 11)) : mhi;
        #pragma unroll
        for (int ni = 0; ni < 4; ni++) {
            int n = n0 + wn + ni * 8 + 2 * cg;
            float b0 = bias[n], b1 = bias[n + 1];
            float v0 = acc[mi][ni][0] + b0;
            float v1 = acc[mi][ni][1] + b1;
            float v2 = acc[mi][ni][2] + b0;
            float v3 = acc[mi][ni][3] + b1;
            if (EPI == 1) {
                v0 = 1.0f / (1.0f + __expf(-v0)); v1 = 1.0f / (1.0f + __expf(-v1));
                v2 = 1.0f / (1.0f + __expf(-v2)); v3 = 1.0f / (1.0f + __expf(-v3));
            } else if (EPI == 2) {
                v0 *= gelu_exact(v0); v1 *= gelu_exact(v1);
                v2 *= gelu_exact(v2); v3 *= gelu_exact(v3);
            } else if (EPI == 3) {
                float2 r0 = *(const float2*)(res + (size_t)mlo * N_ + n);
                float2 r1 = *(const float2*)(res + (size_t)mhi * N_ + n);
                v0 += r0.x; v1 += r0.y; v2 += r1.x; v3 += r1.y;
            }
            if (ROUND) {
                v0 = f2tf(v0); v1 = f2tf(v1); v2 = f2tf(v2); v3 = f2tf(v3);
            }
            *(float2*)(C + (size_t)olo * opitch + n) = make_float2(v0, v1);
            *(float2*)(C + (size_t)ohi * opitch + n) = make_float2(v2, v3);
        }
    }
}

// ---------------- weight prep ----------------
__global__ void round_copy_k(const float* __restrict__ s, float* __restrict__ d, int n4) {
    int i = blockIdx.x * blockDim.x + threadIdx.x;
    if (i >= n4) return;
    float4 v = ((const float4*)s)[i];
    v.x = f2tf(v.x); v.y = f2tf(v.y); v.z = f2tf(v.z); v.w = f2tf(v.w);
    ((float4*)d)[i] = v;
}

__global__ void prep_wc_k(const float* __restrict__ dw_w, float* __restrict__ Wc) {
    int idx = blockIdx.x * blockDim.x + threadIdx.x;
    if (idx >= KCONV * DD * DD) return;
    int o = idx % DD;
    int i = (idx / DD) % DD;
    int k = idx / (DD * DD);
    Wc[idx] = f2tf(dw_w[((size_t)o * DD + i) * KCONV + k]);
}

__global__ void prep_pwt_k(const float* __restrict__ pw_w, float* __restrict__ pwT) {
    int idx = blockIdx.x * blockDim.x + threadIdx.x;
    if (idx >= DD * DD) return;
    int o = idx % DD;
    int i = idx / DD;
    pwT[idx] = f2tf(pw_w[(size_t)o * DD + i]);
}

__global__ void lamprep_k(const float* __restrict__ lam, float* __restrict__ lamc) {
    int d = threadIdx.x + blockIdx.x * blockDim.x;
    if (d >= DD) return;
    float l = lam[d];
    float sp = (l > 15.f) ? l : log1pf(expf(l));
    lamc[d] = -8.0f * sp;
}

__global__ void zero_edges_k(float* __restrict__ pad) {
    int idx = blockIdx.x * blockDim.x + threadIdx.x;
    if (idx >= BB * 8 * (DD / 4)) return;
    int c = idx & 127;
    int rr = idx >> 7;
    int b = rr >> 3, j = rr & 7;
    int p = (j < 4) ? j : (2048 + j);
    ((float4*)(pad + ((size_t)b * SPAD + p) * DD))[c] = make_float4(0.f, 0.f, 0.f, 0.f);
}

// ---------------- gate transform ----------------
__global__ void gates_k(float* __restrict__ R, float* __restrict__ I,
                        const float* __restrict__ xL, const float* __restrict__ lamc) {
    size_t i = (size_t)blockIdx.x * blockDim.x + threadIdx.x;
    if (i >= (size_t)MM * DD) return;
    int d = (int)(i & (DD - 1));
    float a = __expf(lamc[d] * R[i]);
    float b = sqrtf(fmaxf(0.f, 1.0f - a * a)) * (I[i] * xL[i]);
    R[i] = a;
    I[i] = b;
}

// ---------------- chunked linear scan ----------------
__global__ void scanA_k(const float* __restrict__ a, const float* __restrict__ b,
                        float* __restrict__ cA, float* __restrict__ cB) {
    int t = blockIdx.x * blockDim.x + threadIdx.x;
    if (t >= BB * NC * DD) return;
    int d = t & (DD - 1);
    int chunk = (t >> 9) & (NC - 1);
    int batch = t >> 14;
    size_t base = ((size_t)batch * SS + (size_t)chunk * LCH) * DD + d;
    float A = 1.f, Bv = 0.f;
    for (int s = 0; s < LCH; s++) {
        float av = a[base + (size_t)s * DD];
        float bv = b[base + (size_t)s * DD];
        Bv = av * Bv + bv;
        A *= av;
    }
    cA[t] = A; cB[t] = Bv;
}

__global__ void scanB_k(const float* __restrict__ cA, const float* __restrict__ cB,
                        float* __restrict__ pref) {
    int t = blockIdx.x * blockDim.x + threadIdx.x;
    if (t >= BB * DD) return;
    int d = t & (DD - 1);
    int batch = t >> 9;
    float h = 0.f;
    for (int c = 0; c < NC; c++) {
        size_t idx = ((size_t)batch * NC + c) * DD + d;
        pref[idx] = h;
        h = cA[idx] * h + cB[idx];
    }
}

__global__ void scanC_k(const float* __restrict__ a, const float* __restrict__ b,
                        const float* __restrict__ pref, const float* __restrict__ l2,
                        const float* __restrict__ skip, float* __restrict__ x1) {
    int t = blockIdx.x * blockDim.x + threadIdx.x;
    if (t >= BB * NC * DD) return;
    int d = t & (DD - 1);
    int chunk = (t >> 9) & (NC - 1);
    int batch = t >> 14;
    size_t base = ((size_t)batch * SS + (size_t)chunk * LCH) * DD + d;
    float h = pref[t];
    for (int s = 0; s < LCH; s++) {
        size_t idx = base + (size_t)s * DD;
        h = a[idx] * h + b[idx];
        x1[idx] = h * gelu_exact(l2[idx]) + skip[idx];
    }
}

// ---------------- launch ----------------
extern "C" void kernel_launch(void* const* d_in, const int* in_sizes, int n_in,
                              void* d_out, int out_size) {
    const float* x    = (const float*)d_in[0];
    const float* g    = (const float*)d_in[1];
    const float* W1   = (const float*)d_in[2];
    const float* b1   = (const float*)d_in[3];
    const float* W2   = (const float*)d_in[4];
    const float* b2   = (const float*)d_in[5];
    const float* dw_w = (const float*)d_in[6];
    const float* dw_b = (const float*)d_in[7];
    const float* pw_w = (const float*)d_in[8];
    const float* pw_b = (const float*)d_in[9];
    const float* Wi   = (const float*)d_in[10];
    const float* bi   = (const float*)d_in[11];
    const float* Wr   = (const float*)d_in[12];
    const float* br   = (const float*)d_in[13];
    const float* lam  = (const float*)d_in[14];
    const float* Wm1  = (const float*)d_in[15];
    const float* bm1  = (const float*)d_in[16];
    const float* Wm2  = (const float*)d_in[17];
    const float* bm2  = (const float*)d_in[18];
    float* out = (float*)d_out;

    float *xn, *l2, *pad, *conv, *xL, *R, *I, *x1, *xn2, *act;
    float *Wc, *pwT, *cA, *cB, *pref, *lamc;
    float *W1t, *W2t, *Wrt, *Wit, *Wm1t, *Wm2t;
    cudaGetSymbolAddress((void**)&xn,  g_xn);
    cudaGetSymbolAddress((void**)&l2,  g_l2);
    cudaGetSymbolAddress((void**)&pad, g_pad);
    cudaGetSymbolAddress((void**)&conv,g_conv);
    cudaGetSymbolAddress((void**)&xL,  g_xL);
    cudaGetSymbolAddress((void**)&R,   g_R);
    cudaGetSymbolAddress((void**)&I,   g_I);
    cudaGetSymbolAddress((void**)&x1,  g_x1);
    cudaGetSymbolAddress((void**)&xn2, g_xn2);
    cudaGetSymbolAddress((void**)&act, g_act);
    cudaGetSymbolAddress((void**)&Wc,  g_Wc);
    cudaGetSymbolAddress((void**)&pwT, g_pwT);
    cudaGetSymbolAddress((void**)&cA,  g_cA);
    cudaGetSymbolAddress((void**)&cB,  g_cB);
    cudaGetSymbolAddress((void**)&pref,g_pref);
    cudaGetSymbolAddress((void**)&lamc,g_lamc);
    cudaGetSymbolAddress((void**)&W1t, g_W1t);
    cudaGetSymbolAddress((void**)&W2t, g_W2t);
    cudaGetSymbolAddress((void**)&Wrt, g_Wrt);
    cudaGetSymbolAddress((void**)&Wit, g_Wit);
    cudaGetSymbolAddress((void**)&Wm1t,g_Wm1t);
    cudaGetSymbolAddress((void**)&Wm2t,g_Wm2t);

    cudaFuncSetAttribute(tgemm<0,false,true ,true >, cudaFuncAttributeMaxDynamicSharedMemorySize, SMEMSZ);
    cudaFuncSetAttribute(tgemm<0,false,false,false>, cudaFuncAttributeMaxDynamicSharedMemorySize, SMEMSZ);
    cudaFuncSetAttribute(tgemm<0,true ,true ,false>, cudaFuncAttributeMaxDynamicSharedMemorySize, SMEMSZ);
    cudaFuncSetAttribute(tgemm<0,false,true ,false>, cudaFuncAttributeMaxDynamicSharedMemorySize, SMEMSZ);
    cudaFuncSetAttribute(tgemm<1,false,false,false>, cudaFuncAttributeMaxDynamicSharedMemorySize, SMEMSZ);
    cudaFuncSetAttribute(tgemm<2,false,true ,false>, cudaFuncAttributeMaxDynamicSharedMemorySize, SMEMSZ);
    cudaFuncSetAttribute(tgemm<3,false,false,false>, cudaFuncAttributeMaxDynamicSharedMemorySize, SMEMSZ);

    dim3 g512(DD / BN, MM / BM);
    dim3 g2048(DM / BN, MM / BM);

    round_copy_k<<<(DD*DD/4 + 255)/256, 256>>>(W1,  W1t,  DD*DD/4);
    round_copy_k<<<(DD*DD/4 + 255)/256, 256>>>(W2,  W2t,  DD*DD/4);
    round_copy_k<<<(DD*DD/4 + 255)/256, 256>>>(Wr,  Wrt,  DD*DD/4);
    round_copy_k<<<(DD*DD/4 + 255)/256, 256>>>(Wi,  Wit,  DD*DD/4);
    round_copy_k<<<(DD*DM/4 + 255)/256, 256>>>(Wm1, Wm1t, DD*DM/4);
    round_copy_k<<<(DD*DM/4 + 255)/256, 256>>>(Wm2, Wm2t, DD*DM/4);
    prep_wc_k<<<(KCONV * DD * DD + 255) / 256, 256>>>(dw_w, Wc);
    prep_pwt_k<<<(DD * DD + 255) / 256, 256>>>(pw_w, pwT);
    lamprep_k<<<2, 256>>>(lam, lamc);
    zero_edges_k<<<(BB * 8 * (DD/4) + 255) / 256, 256>>>(pad);

    rms_k<<<MM, 128>>>(x, g, xn);
    tgemm<0,false,true ,true ><<<g512, 256, SMEMSZ>>>(xn, W1t, b1, nullptr, pad, MM, DD, DD);
    tgemm<0,false,false,false><<<g512, 256, SMEMSZ>>>(xn, W2t, b2, nullptr, l2, MM, DD, DD);
    tgemm<0,true ,true ,false><<<g512, 256, SMEMSZ>>>(pad, Wc, dw_b, nullptr, conv, MM, DD, KCONV * DD);
    tgemm<0,false,true ,false><<<g512, 256, SMEMSZ>>>(conv, pwT, pw_b, nullptr, xL, MM, DD, DD);
    tgemm<1,false,false,false><<<g512, 256, SMEMSZ>>>(xL, Wrt, br, nullptr, R, MM, DD, DD);
    tgemm<1,false,false,false><<<g512, 256, SMEMSZ>>>(xL, Wit, bi, nullptr, I, MM, DD, DD);
    gates_k<<<((size_t)MM * DD + 255) / 256, 256>>>(R, I, xL, lamc);
    scanA_k<<<(BB * NC * DD + 255) / 256, 256>>>(R, I, cA, cB);
    scanB_k<<<(BB * DD + 255) / 256, 256>>>(cA, cB, pref);
    scanC_k<<<(BB * NC * DD + 255) / 256, 256>>>(R, I, pref, l2, x, x1);

    rms_k<<<MM, 128>>>(x1, g, xn2);
    tgemm<2,false,true ,false><<<g2048, 256, SMEMSZ>>>(xn2, Wm1t, bm1, nullptr, act, MM, DM, DD);
    tgemm<3,false,false,false><<<g512, 256, SMEMSZ>>>(act, Wm2t, bm2, x1, out, MM, DD, DM);
}

// round 4
// speedup vs baseline: 5.3310x; 1.8473x over previous
#include <cuda_runtime.h>
#include <cuda_bf16.h>
#include <math.h>

// ---------------- problem constants ----------------
#define BB    8
#define SS    2048
#define DD    512
#define MM    (BB*SS)          // 16384 rows
#define DM    (DD*4)           // 2048
#define KCONV 9
#define SPAD  (SS+8)           // 2056 padded rows per batch
#define NC    32               // scan chunks
#define LCH   (SS/NC)          // 64 steps per chunk

typedef __nv_bfloat16 bf16;
typedef __nv_bfloat162 bf162;

// ---------------- scratch (device globals; no allocs allowed) ----------------
__device__ bf16  g_xn  [MM*DD];
__device__ float g_l2  [MM*DD];
__device__ bf16  g_pad [BB*SPAD*DD];
__device__ bf16  g_conv[MM*DD];
__device__ bf16  g_xL  [MM*DD];
__device__ float g_R   [MM*DD];
__device__ float g_I   [MM*DD];
__device__ float g_x1  [MM*DD];
__device__ bf16  g_xn2 [MM*DD];
__device__ bf16  g_act [MM*DM];
__device__ bf16  g_Wc  [KCONV*DD*DD];
__device__ bf16  g_pwT [DD*DD];
__device__ float g_cA  [BB*NC*DD];
__device__ float g_cB  [BB*NC*DD];
__device__ float g_pref[BB*NC*DD];
__device__ float g_lamc[DD];
__device__ bf16  g_W1t [DD*DD];
__device__ bf16  g_W2t [DD*DD];
__device__ bf16  g_Wrt [DD*DD];
__device__ bf16  g_Wit [DD*DD];
__device__ bf16  g_Wm1t[DD*DM];
__device__ bf16  g_Wm2t[DD*DM];

// ---------------- helpers ----------------
__device__ __forceinline__ float gelu_exact(float v) {
    return 0.5f * v * (1.0f + erff(v * 0.70710678118654752f));
}

__device__ __forceinline__ void mma16(float* c, const unsigned* a, const unsigned* b) {
    asm volatile(
        "mma.sync.aligned.m16n8k16.row.col.f32.bf16.bf16.f32 "
        "{%0,%1,%2,%3}, {%4,%5,%6,%7}, {%8,%9}, {%0,%1,%2,%3};"
        : "+f"(c[0]), "+f"(c[1]), "+f"(c[2]), "+f"(c[3])
        : "r"(a[0]), "r"(a[1]), "r"(a[2]), "r"(a[3]), "r"(b[0]), "r"(b[1]));
}

__device__ __forceinline__ void ldsm4(unsigned* r, unsigned addr) {
    asm volatile("ldmatrix.sync.aligned.m8n8.x4.shared.b16 {%0,%1,%2,%3}, [%4];"
                 : "=r"(r[0]), "=r"(r[1]), "=r"(r[2]), "=r"(r[3]) : "r"(addr));
}
__device__ __forceinline__ void ldsm2t(unsigned* r, unsigned addr) {
    asm volatile("ldmatrix.sync.aligned.m8n8.x2.trans.shared.b16 {%0,%1}, [%2];"
                 : "=r"(r[0]), "=r"(r[1]) : "r"(addr));
}

__device__ __forceinline__ void cpa16(unsigned s, const void* g) {
    asm volatile("cp.async.ca.shared.global [%0], [%1], 16;" :: "r"(s), "l"(g));
}
__device__ __forceinline__ void cpa_commit() {
    asm volatile("cp.async.commit_group;");
}

// ---------------- RMS norm (f32 in -> bf16 out, feeds GEMMs) ----------------
__global__ void rms_k(const float* __restrict__ x, const float* __restrict__ g,
                      bf16* __restrict__ o) {
    int row = blockIdx.x;
    int t = threadIdx.x;
    const float4* xr = (const float4*)(x + (size_t)row * DD);
    float4 v = xr[t];
    float s = v.x*v.x + v.y*v.y + v.z*v.z + v.w*v.w;
    #pragma unroll
    for (int off = 16; off; off >>= 1) s += __shfl_xor_sync(0xffffffffu, s, off);
    __shared__ float ws[4];
    if ((t & 31) == 0) ws[t >> 5] = s;
    __syncthreads();
    float tot = ws[0] + ws[1] + ws[2] + ws[3];
    float sc = 22.627416997969522f / (sqrtf(tot) + 1e-6f);
    float4 gv = ((const float4*)g)[t];
    bf162* ob = (bf162*)(o + (size_t)row * DD);
    ob[2*t]   = __floats2bfloat162_rn(v.x * sc * gv.x, v.y * sc * gv.y);
    ob[2*t+1] = __floats2bfloat162_rn(v.z * sc * gv.z, v.w * sc * gv.w);
}

// ---------------- bf16 tensor-core GEMM ----------------
// EPI: 0 = bias, 1 = sigmoid, 2 = gelu(v)*v, 3 = +res
// CONV: A read from padded activations with tap offsets (K'=9*512)
// OUTBF: output bf16 (feeds another GEMM), else f32
// PADOUT: write into padded buffer layout (row -> row + 4 + 8*(row>>11)), bf16
#define BM 128
#define BN 128
#define BK 32
#define APITCH 40      // elements; 80B rows: 16B-aligned, conflict-free for ldsm
#define BPITCH 136     // elements; 272B rows
#define NSTG 3
#define SMEMSZ (NSTG*(BM*APITCH + BK*BPITCH)*2)

template <int EPI, bool CONV, bool OUTBF, bool PADOUT>
__global__ void __launch_bounds__(256, 2)
tgemm(const bf16* __restrict__ A, const bf16* __restrict__ Bw,
      const float* __restrict__ bias, const float* __restrict__ res,
      void* __restrict__ Cv, int M_, int N_, int K_) {
    extern __shared__ bf16 smb[];
    bf16 (*As)[BM][APITCH] = (bf16(*)[BM][APITCH])smb;
    bf16 (*Bs)[BK][BPITCH] = (bf16(*)[BK][BPITCH])(smb + NSTG * BM * APITCH);

    const int tid = threadIdx.x;
    const int m0 = blockIdx.y * BM;
    const int n0 = blockIdx.x * BN;
    const int warp = tid >> 5, lane = tid & 31;
    const int wm = (warp >> 2) * 64;
    const int wn = (warp & 3) * 32;
    const int padbase = CONV ? (m0 + 8 * (m0 / SS)) : 0;

    // cp.async staging
    const int arow = tid >> 1;          // 0..127
    const int acol = (tid & 1) * 16;    // 0 or 16
    const int brow = tid >> 3;          // 0..31
    const int bcol = (tid & 7) * 16;    // 0..112

    // ldmatrix lane offsets
    const int a_rowoff = (lane & 7) + ((lane >> 3) & 1) * 8;
    const int a_coloff = (lane >> 4) * 8;
    const int b_rowoff = lane & 15;

    const unsigned sA = (unsigned)__cvta_generic_to_shared(smb);
    const unsigned sB = (unsigned)__cvta_generic_to_shared(smb + NSTG * BM * APITCH);
    const unsigned aBase = sA + (unsigned)(((wm + a_rowoff) * APITCH + a_coloff) * 2);
    const unsigned bBase = sB + (unsigned)((b_rowoff * BPITCH + wn) * 2);

    const int nit = K_ / BK;

    auto prefetch = [&](int it, int buf) {
        int k0 = it * BK;
        const bf16* ga;
        if (CONV) {
            int tap = k0 >> 9;
            int kin = k0 & 511;
            ga = A + (size_t)(padbase + arow + tap) * DD + kin + acol;
        } else {
            ga = A + (size_t)(m0 + arow) * K_ + k0 + acol;
        }
        unsigned da = (unsigned)__cvta_generic_to_shared(&As[buf][arow][acol]);
        cpa16(da, ga);
        cpa16(da + 16, ga + 8);
        const bf16* gb = Bw + (size_t)(k0 + brow) * N_ + n0 + bcol;
        unsigned db = (unsigned)__cvta_generic_to_shared(&Bs[buf][brow][bcol]);
        cpa16(db, gb);
        cpa16(db + 16, gb + 8);
    };

    float acc[4][4][4] = {};

    prefetch(0, 0);
    cpa_commit();
    if (nit > 1) { prefetch(1, 1); cpa_commit(); }

    for (int it = 0; it < nit; it++) {
        if (it + 1 < nit) asm volatile("cp.async.wait_group 1;");
        else              asm volatile("cp.async.wait_group 0;");
        __syncthreads();
        if (it + 2 < nit) { prefetch(it + 2, (it + 2) % NSTG); cpa_commit(); }

        const int buf = it % NSTG;
        const unsigned ab = aBase + (unsigned)(buf * BM * APITCH * 2);
        const unsigned bb = bBase + (unsigned)(buf * BK * BPITCH * 2);
        #pragma unroll
        for (int t = 0; t < 2; t++) {
            unsigned af[4][4], bfr[4][2];
            #pragma unroll
            for (int mi = 0; mi < 4; mi++)
                ldsm4(af[mi], ab + (unsigned)((mi * 16 * APITCH + 16 * t) * 2));
            #pragma unroll
            for (int ni = 0; ni < 4; ni++)
                ldsm2t(bfr[ni], bb + (unsigned)((16 * t * BPITCH + 8 * ni) * 2));
            #pragma unroll
            for (int mi = 0; mi < 4; mi++)
                #pragma unroll
                for (int ni = 0; ni < 4; ni++)
                    mma16(acc[mi][ni], af[mi], bfr[ni]);
        }
        __syncthreads();
    }

    // epilogue
    const int r = lane >> 2, cg = lane & 3;
    const int opitch = PADOUT ? DD : N_;
    #pragma unroll
    for (int mi = 0; mi < 4; mi++) {
        int mlo = m0 + wm + mi * 16 + r;
        int mhi = mlo + 8;
        int olo = PADOUT ? (mlo + 4 + 8 * (mlo >> 11)) : mlo;
        int ohi = PADOUT ? (mhi + 4 + 8 * (mhi >> 11)) : mhi;
        #pragma unroll
        for (int ni = 0; ni < 4; ni++) {
            int n = n0 + wn + ni * 8 + 2 * cg;
            float b0 = bias[n], b1 = bias[n + 1];
            float v0 = acc[mi][ni][0] + b0;
            float v1 = acc[mi][ni][1] + b1;
            float v2 = acc[mi][ni][2] + b0;
            float v3 = acc[mi][ni][3] + b1;
            if (EPI == 1) {
                v0 = 1.0f / (1.0f + __expf(-v0)); v1 = 1.0f / (1.0f + __expf(-v1));
                v2 = 1.0f / (1.0f + __expf(-v2)); v3 = 1.0f / (1.0f + __expf(-v3));
            } else if (EPI == 2) {
                v0 *= gelu_exact(v0); v1 *= gelu_exact(v1);
                v2 *= gelu_exact(v2); v3 *= gelu_exact(v3);
            } else if (EPI == 3) {
                float2 r0 = *(const float2*)(res + (size_t)mlo * N_ + n);
                float2 r1 = *(const float2*)(res + (size_t)mhi * N_ + n);
                v0 += r0.x; v1 += r0.y; v2 += r1.x; v3 += r1.y;
            }
            if (OUTBF) {
                bf16* C = (bf16*)Cv;
                *(bf162*)(C + (size_t)olo * opitch + n) = __floats2bfloat162_rn(v0, v1);
                *(bf162*)(C + (size_t)ohi * opitch + n) = __floats2bfloat162_rn(v2, v3);
            } else {
                float* C = (float*)Cv;
                *(float2*)(C + (size_t)olo * opitch + n) = make_float2(v0, v1);
                *(float2*)(C + (size_t)ohi * opitch + n) = make_float2(v2, v3);
            }
        }
    }
}

// ---------------- weight prep ----------------
__global__ void cvt_copy_k(const float* __restrict__ s, bf16* __restrict__ d, int n4) {
    int i = blockIdx.x * blockDim.x + threadIdx.x;
    if (i >= n4) return;
    float4 v = ((const float4*)s)[i];
    ((bf162*)d)[2*i]   = __floats2bfloat162_rn(v.x, v.y);
    ((bf162*)d)[2*i+1] = __floats2bfloat162_rn(v.z, v.w);
}

__global__ void prep_wc_k(const float* __restrict__ dw_w, bf16* __restrict__ Wc) {
    int idx = blockIdx.x * blockDim.x + threadIdx.x;
    if (idx >= KCONV * DD * DD) return;
    int o = idx % DD;
    int i = (idx / DD) % DD;
    int k = idx / (DD * DD);
    Wc[idx] = __float2bfloat16(dw_w[((size_t)o * DD + i) * KCONV + k]);
}

__global__ void prep_pwt_k(const float* __restrict__ pw_w, bf16* __restrict__ pwT) {
    int idx = blockIdx.x * blockDim.x + threadIdx.x;
    if (idx >= DD * DD) return;
    int o = idx % DD;
    int i = idx / DD;
    pwT[idx] = __float2bfloat16(pw_w[(size_t)o * DD + i]);
}

__global__ void lamprep_k(const float* __restrict__ lam, float* __restrict__ lamc) {
    int d = threadIdx.x + blockIdx.x * blockDim.x;
    if (d >= DD) return;
    float l = lam[d];
    float sp = (l > 15.f) ? l : log1pf(expf(l));
    lamc[d] = -8.0f * sp;
}

// zero the 8 halo rows per batch in the padded bf16 buffer
__global__ void zero_edges_k(bf16* __restrict__ pad) {
    int idx = blockIdx.x * blockDim.x + threadIdx.x;   // 4096 chunks of 8 bf16
    if (idx >= BB * 8 * (DD / 8)) return;
    int c = idx & 63;
    int rr = idx >> 6;
    int b = rr >> 3, j = rr & 7;
    int p = (j < 4) ? j : (2048 + j);
    uint4 z = make_uint4(0, 0, 0, 0);
    *(uint4*)(pad + ((size_t)b * SPAD + p) * DD + c * 8) = z;
}

// ---------------- gate transform: R,I -> a,b ----------------
__global__ void gates_k(float* __restrict__ R, float* __restrict__ I,
                        const bf16* __restrict__ xL, const float* __restrict__ lamc) {
    size_t i = (size_t)blockIdx.x * blockDim.x + threadIdx.x;
    if (i >= (size_t)MM * DD) return;
    int d = (int)(i & (DD - 1));
    float a = __expf(lamc[d] * R[i]);
    float b = sqrtf(fmaxf(0.f, 1.0f - a * a)) * (I[i] * __bfloat162float(xL[i]));
    R[i] = a;
    I[i] = b;
}

// ---------------- chunked linear scan ----------------
__global__ void scanA_k(const float* __restrict__ a, const float* __restrict__ b,
                        float* __restrict__ cA, float* __restrict__ cB) {
    int t = blockIdx.x * blockDim.x + threadIdx.x;
    if (t >= BB * NC * DD) return;
    int d = t & (DD - 1);
    int chunk = (t >> 9) & (NC - 1);
    int batch = t >> 14;
    size_t base = ((size_t)batch * SS + (size_t)chunk * LCH) * DD + d;
    float A = 1.f, Bv = 0.f;
    for (int s = 0; s < LCH; s++) {
        float av = a[base + (size_t)s * DD];
        float bv = b[base + (size_t)s * DD];
        Bv = av * Bv + bv;
        A *= av;
    }
    cA[t] = A; cB[t] = Bv;
}

__global__ void scanB_k(const float* __restrict__ cA, const float* __restrict__ cB,
                        float* __restrict__ pref) {
    int t = blockIdx.x * blockDim.x + threadIdx.x;
    if (t >= BB * DD) return;
    int d = t & (DD - 1);
    int batch = t >> 9;
    float h = 0.f;
    for (int c = 0; c < NC; c++) {
        size_t idx = ((size_t)batch * NC + c) * DD + d;
        pref[idx] = h;
        h = cA[idx] * h + cB[idx];
    }
}

__global__ void scanC_k(const float* __restrict__ a, const float* __restrict__ b,
                        const float* __restrict__ pref, const float* __restrict__ l2,
                        const float* __restrict__ skip, float* __restrict__ x1) {
    int t = blockIdx.x * blockDim.x + threadIdx.x;
    if (t >= BB * NC * DD) return;
    int d = t & (DD - 1);
    int chunk = (t >> 9) & (NC - 1);
    int batch = t >> 14;
    size_t base = ((size_t)batch * SS + (size_t)chunk * LCH) * DD + d;
    float h = pref[t];
    for (int s = 0; s < LCH; s++) {
        size_t idx = base + (size_t)s * DD;
        h = a[idx] * h + b[idx];
        x1[idx] = h * gelu_exact(l2[idx]) + skip[idx];
    }
}

// ---------------- launch ----------------
extern "C" void kernel_launch(void* const* d_in, const int* in_sizes, int n_in,
                              void* d_out, int out_size) {
    const float* x    = (const float*)d_in[0];
    const float* g    = (const float*)d_in[1];
    const float* W1   = (const float*)d_in[2];
    const float* b1   = (const float*)d_in[3];
    const float* W2   = (const float*)d_in[4];
    const float* b2   = (const float*)d_in[5];
    const float* dw_w = (const float*)d_in[6];
    const float* dw_b = (const float*)d_in[7];
    const float* pw_w = (const float*)d_in[8];
    const float* pw_b = (const float*)d_in[9];
    const float* Wi   = (const float*)d_in[10];
    const float* bi   = (const float*)d_in[11];
    const float* Wr   = (const float*)d_in[12];
    const float* br   = (const float*)d_in[13];
    const float* lam  = (const float*)d_in[14];
    const float* Wm1  = (const float*)d_in[15];
    const float* bm1  = (const float*)d_in[16];
    const float* Wm2  = (const float*)d_in[17];
    const float* bm2  = (const float*)d_in[18];
    float* out = (float*)d_out;

    bf16 *xn, *pad, *conv, *xL, *xn2, *act, *Wc, *pwT;
    bf16 *W1t, *W2t, *Wrt, *Wit, *Wm1t, *Wm2t;
    float *l2, *R, *I, *x1, *cA, *cB, *pref, *lamc;
    cudaGetSymbolAddress((void**)&xn,  g_xn);
    cudaGetSymbolAddress((void**)&l2,  g_l2);
    cudaGetSymbolAddress((void**)&pad, g_pad);
    cudaGetSymbolAddress((void**)&conv,g_conv);
    cudaGetSymbolAddress((void**)&xL,  g_xL);
    cudaGetSymbolAddress((void**)&R,   g_R);
    cudaGetSymbolAddress((void**)&I,   g_I);
    cudaGetSymbolAddress((void**)&x1,  g_x1);
    cudaGetSymbolAddress((void**)&xn2, g_xn2);
    cudaGetSymbolAddress((void**)&act, g_act);
    cudaGetSymbolAddress((void**)&Wc,  g_Wc);
    cudaGetSymbolAddress((void**)&pwT, g_pwT);
    cudaGetSymbolAddress((void**)&cA,  g_cA);
    cudaGetSymbolAddress((void**)&cB,  g_cB);
    cudaGetSymbolAddress((void**)&pref,g_pref);
    cudaGetSymbolAddress((void**)&lamc,g_lamc);
    cudaGetSymbolAddress((void**)&W1t, g_W1t);
    cudaGetSymbolAddress((void**)&W2t, g_W2t);
    cudaGetSymbolAddress((void**)&Wrt, g_Wrt);
    cudaGetSymbolAddress((void**)&Wit, g_Wit);
    cudaGetSymbolAddress((void**)&Wm1t,g_Wm1t);
    cudaGetSymbolAddress((void**)&Wm2t,g_Wm2t);

    cudaFuncSetAttribute(tgemm<0,false,true ,true >, cudaFuncAttributeMaxDynamicSharedMemorySize, SMEMSZ);
    cudaFuncSetAttribute(tgemm<0,false,false,false>, cudaFuncAttributeMaxDynamicSharedMemorySize, SMEMSZ);
    cudaFuncSetAttribute(tgemm<0,true ,true ,false>, cudaFuncAttributeMaxDynamicSharedMemorySize, SMEMSZ);
    cudaFuncSetAttribute(tgemm<0,false,true ,false>, cudaFuncAttributeMaxDynamicSharedMemorySize, SMEMSZ);
    cudaFuncSetAttribute(tgemm<1,false,false,false>, cudaFuncAttributeMaxDynamicSharedMemorySize, SMEMSZ);
    cudaFuncSetAttribute(tgemm<2,false,true ,false>, cudaFuncAttributeMaxDynamicSharedMemorySize, SMEMSZ);
    cudaFuncSetAttribute(tgemm<3,false,false,false>, cudaFuncAttributeMaxDynamicSharedMemorySize, SMEMSZ);

    dim3 g512(DD / BN, MM / BM);
    dim3 g2048(DM / BN, MM / BM);

    cvt_copy_k<<<(DD*DD/4 + 255)/256, 256>>>(W1,  W1t,  DD*DD/4);
    cvt_copy_k<<<(DD*DD/4 + 255)/256, 256>>>(W2,  W2t,  DD*DD/4);
    cvt_copy_k<<<(DD*DD/4 + 255)/256, 256>>>(Wr,  Wrt,  DD*DD/4);
    cvt_copy_k<<<(DD*DD/4 + 255)/256, 256>>>(Wi,  Wit,  DD*DD/4);
    cvt_copy_k<<<(DD*DM/4 + 255)/256, 256>>>(Wm1, Wm1t, DD*DM/4);
    cvt_copy_k<<<(DD*DM/4 + 255)/256, 256>>>(Wm2, Wm2t, DD*DM/4);
    prep_wc_k<<<(KCONV * DD * DD + 255) / 256, 256>>>(dw_w, Wc);
    prep_pwt_k<<<(DD * DD + 255) / 256, 256>>>(pw_w, pwT);
    lamprep_k<<<2, 256>>>(lam, lamc);
    zero_edges_k<<<(BB * 8 * (DD/8) + 255) / 256, 256>>>(pad);

    // block 1
    rms_k<<<MM, 128>>>(x, g, xn);
    tgemm<0,false,true ,true ><<<g512, 256, SMEMSZ>>>(xn, W1t, b1, nullptr, pad, MM, DD, DD);
    tgemm<0,false,false,false><<<g512, 256, SMEMSZ>>>(xn, W2t, b2, nullptr, l2, MM, DD, DD);
    tgemm<0,true ,true ,false><<<g512, 256, SMEMSZ>>>(pad, Wc, dw_b, nullptr, conv, MM, DD, KCONV * DD);
    tgemm<0,false,true ,false><<<g512, 256, SMEMSZ>>>(conv, pwT, pw_b, nullptr, xL, MM, DD, DD);
    tgemm<1,false,false,false><<<g512, 256, SMEMSZ>>>(xL, Wrt, br, nullptr, R, MM, DD, DD);
    tgemm<1,false,false,false><<<g512, 256, SMEMSZ>>>(xL, Wit, bi, nullptr, I, MM, DD, DD);
    gates_k<<<((size_t)MM * DD + 255) / 256, 256>>>(R, I, xL, lamc);
    scanA_k<<<(BB * NC * DD + 255) / 256, 256>>>(R, I, cA, cB);
    scanB_k<<<(BB * DD + 255) / 256, 256>>>(cA, cB, pref);
    scanC_k<<<(BB * NC * DD + 255) / 256, 256>>>(R, I, pref, l2, x, x1);

    // block 2 (MLP)
    rms_k<<<MM, 128>>>(x1, g, xn2);
    tgemm<2,false,true ,false><<<g2048, 256, SMEMSZ>>>(xn2, Wm1t, bm1, nullptr, act, MM, DM, DD);
    tgemm<3,false,false,false><<<g512, 256, SMEMSZ>>>(act, Wm2t, bm2, x1, out, MM, DD, DM);
}